// round 2
// baseline (speedup 1.0000x reference)
#include <cuda_runtime.h>
#include <cuda_bf16.h>

#define DH 384
#define DG 192
#define TT 48
#define BB 96
#define NTH 384
#define NW 12
#define LAM 0.9f
#define ETA 0.5f
#define LN_EPS 1e-5f

// ---------------- device scratch (allocation-free rule) ----------------
__device__ float WT_g[DH * DH];            // W_h transposed: WT[j*DH + i] = W_h[i*DH + j]
__device__ float WGT_g[DG * DH];           // W_g transposed: WGT[i*DH + j] = W_g[j*DG + i]
__device__ float ZP_g[(size_t)TT * BB * DH]; // z @ W_g^T + b_h

// ---------------- transpose prep ----------------
__global__ void transpose_k(const float* __restrict__ src, int rows, int cols, int which) {
    __shared__ float tile[32][33];
    float* dst = (which == 0) ? WT_g : WGT_g;
    int c0 = blockIdx.x * 32, r0 = blockIdx.y * 32;
    int tx = threadIdx.x, ty = threadIdx.y;
#pragma unroll
    for (int k = 0; k < 4; k++)
        tile[ty + 8 * k][tx] = src[(size_t)(r0 + ty + 8 * k) * cols + c0 + tx];
    __syncthreads();
#pragma unroll
    for (int k = 0; k < 4; k++)
        dst[(size_t)(c0 + ty + 8 * k) * rows + r0 + tx] = tile[tx][ty + 8 * k];
}

// ---------------- z-projection prep: ZP[t][b][j] = sum_i z[t][b][i] * W_g[j][i] + b_h[j] ----------------
__global__ void zp_kernel(const float* __restrict__ z, const float* __restrict__ bh) {
    __shared__ __align__(16) float zs[16 * DG];
    int t = blockIdx.x / 6, bc = blockIdx.x % 6;
    int j = threadIdx.x;
    const float* zsrc = z + ((size_t)t * BB + bc * 16) * DG;
    for (int idx = j; idx < 16 * DG; idx += NTH) zs[idx] = zsrc[idx];
    __syncthreads();
    float acc[16];
    float b0 = bh[j];
#pragma unroll
    for (int m = 0; m < 16; m++) acc[m] = b0;
    const float4* zs4 = (const float4*)zs;
    for (int i4 = 0; i4 < DG / 4; i4++) {
        float w0 = WGT_g[(size_t)(4 * i4 + 0) * DH + j];
        float w1 = WGT_g[(size_t)(4 * i4 + 1) * DH + j];
        float w2 = WGT_g[(size_t)(4 * i4 + 2) * DH + j];
        float w3 = WGT_g[(size_t)(4 * i4 + 3) * DH + j];
#pragma unroll
        for (int m = 0; m < 16; m++) {
            float4 zv = zs4[m * (DG / 4) + i4];
            acc[m] = fmaf(zv.x, w0, acc[m]);
            acc[m] = fmaf(zv.y, w1, acc[m]);
            acc[m] = fmaf(zv.z, w2, acc[m]);
            acc[m] = fmaf(zv.w, w3, acc[m]);
        }
    }
    float* dst = ZP_g + ((size_t)t * BB + bc * 16) * DH + j;
#pragma unroll
    for (int m = 0; m < 16; m++) dst[(size_t)m * DH] = acc[m];
}

// ---------------- block helpers ----------------

// relu(layernorm(v)): v is one element per thread (DH == blockDim.x)
__device__ __forceinline__ float block_ln_relu(float v, float gj, float bj,
                                               float* red, float* scal) {
    int w = threadIdx.x >> 5, l = threadIdx.x & 31;
    float s = v, q = v * v;
#pragma unroll
    for (int o = 16; o; o >>= 1) {
        s += __shfl_xor_sync(0xffffffffu, s, o);
        q += __shfl_xor_sync(0xffffffffu, q, o);
    }
    __syncthreads();  // protect red reuse from prior call
    if (l == 0) { red[2 * w] = s; red[2 * w + 1] = q; }
    __syncthreads();
    if (threadIdx.x == 0) {
        float ss = 0.f, qq = 0.f;
#pragma unroll
        for (int i = 0; i < NW; i++) { ss += red[2 * i]; qq += red[2 * i + 1]; }
        float mean = ss * (1.f / DH);
        float var = qq * (1.f / DH) - mean * mean;
        scal[0] = mean;
        scal[1] = rsqrtf(var + LN_EPS);
    }
    __syncthreads();
    float r = (v - scal[0]) * scal[1] * gj + bj;
    return fmaxf(r, 0.f);
}

// cosine gate: scal[2] = 1 - a^2, scal[3] = a
__device__ __forceinline__ void block_gate(float d, float p, float q, float kexp,
                                           float* red, float* scal) {
    int w = threadIdx.x >> 5, l = threadIdx.x & 31;
#pragma unroll
    for (int o = 16; o; o >>= 1) {
        d += __shfl_xor_sync(0xffffffffu, d, o);
        p += __shfl_xor_sync(0xffffffffu, p, o);
        q += __shfl_xor_sync(0xffffffffu, q, o);
    }
    __syncthreads();
    if (l == 0) { red[3 * w] = d; red[3 * w + 1] = p; red[3 * w + 2] = q; }
    __syncthreads();
    if (threadIdx.x == 0) {
        float dd = 0.f, pp = 0.f, qq = 0.f;
#pragma unroll
        for (int i = 0; i < NW; i++) {
            dd += red[3 * i]; pp += red[3 * i + 1]; qq += red[3 * i + 2];
        }
        float n1 = fmaxf(sqrtf(pp), 1e-6f);
        float n2 = fmaxf(sqrtf(qq), 1e-6f);
        float R = dd / (n1 * n2);
        R = fminf(fmaxf(R, 0.f), 1.f);
        float a = 1.f - powf(1.f - R, kexp);
        scal[2] = 1.f - a * a;
        scal[3] = a;
    }
    __syncthreads();
}

// h_base[tid] = sum_j W_h[tid][j] * hs[j] + ZP[t][b][tid]
// Split: thread (q,c) with q=tid/96, c=tid%96 accumulates outputs 4c..4c+3 over j in [96q, 96q+96)
__device__ __forceinline__ float step_gemv(const float* hs, float* part, int t, int b) {
    int tid = threadIdx.x;
    int q = tid / 96, c = tid % 96;
    const float4* WT4 = (const float4*)WT_g;
    const float4* hs4 = (const float4*)hs;
    float4 acc = make_float4(0.f, 0.f, 0.f, 0.f);
    int jb = q * 24;
#pragma unroll 4
    for (int jj = 0; jj < 24; jj++) {
        float4 hv = hs4[jb + jj];
        int j = (jb + jj) * 4;
        float4 w0 = WT4[(size_t)(j + 0) * 96 + c];
        float4 w1 = WT4[(size_t)(j + 1) * 96 + c];
        float4 w2 = WT4[(size_t)(j + 2) * 96 + c];
        float4 w3 = WT4[(size_t)(j + 3) * 96 + c];
        acc.x = fmaf(hv.x, w0.x, fmaf(hv.y, w1.x, fmaf(hv.z, w2.x, fmaf(hv.w, w3.x, acc.x))));
        acc.y = fmaf(hv.x, w0.y, fmaf(hv.y, w1.y, fmaf(hv.z, w2.y, fmaf(hv.w, w3.y, acc.y))));
        acc.z = fmaf(hv.x, w0.z, fmaf(hv.y, w1.z, fmaf(hv.z, w2.z, fmaf(hv.w, w3.z, acc.z))));
        acc.w = fmaf(hv.x, w0.w, fmaf(hv.y, w1.w, fmaf(hv.z, w2.w, fmaf(hv.w, w3.w, acc.w))));
    }
    __syncthreads();  // prior readers of part are done
    ((float4*)part)[tid] = acc;  // partf[q*384 + 4c + comp]
    __syncthreads();
    float hb = ZP_g[((size_t)t * BB + b) * DH + tid];
#pragma unroll
    for (int q2 = 0; q2 < 4; q2++) hb += part[q2 * DH + tid];
    return hb;
}

// ---------------- main recurrence: one CTA per batch ----------------
__global__ void __launch_bounds__(NTH, 1)
rnn_kernel(const float* __restrict__ lng, const float* __restrict__ lnb,
           const float* __restrict__ alpha, float* __restrict__ out) {
    extern __shared__ float sm[];
    float* hist   = sm;                 // 47*384
    float* hs     = hist + 47 * DH;     // 384
    float* part   = hs + DH;            // 4*384
    float* dots   = part + 4 * DH;      // 48
    float* lampow = dots + 48;          // 48
    float* red    = lampow + 48;        // 40 (36 used)
    float* scal   = red + 40;           // 8

    const int b = blockIdx.x;
    const int tid = threadIdx.x;
    const int w = tid >> 5, l = tid & 31;

    float alf = alpha[0];
    float kexp = (alf >= 0.f) ? (1.f + log1pf(expf(alf)))
                              : (1.f / (1.f + log1pf(expf(-alf))));
    float gj = lng[tid], bj = lnb[tid];

    if (tid < TT) lampow[tid] = ETA * powf(LAM, (float)tid);
    hs[tid] = 0.f;  // h0 = 0
    __syncthreads();

    for (int t = 0; t < TT; t++) {
        float hb = step_gemv(hs, part, t, b);
        float hcur = block_ln_relu(hb, gj, bj, red, scal);
        hs[tid] = hcur;
        __syncthreads();

        const bool fin = (t == TT - 1);
        const int nh = fin ? (TT - 1) : t;       // history length in use
        const int dbase = fin ? (TT - 2) : (t - 1);  // coef exponent = dbase - tau

        for (int s = 0; s < 3; s++) {
            // dots[tau] = eta * lam^(dbase-tau) * (h_tau . h_s)
            for (int tau = w; tau < nh; tau += NW) {
                float d = 0.f;
                const float* hrow = hist + (size_t)tau * DH;
                for (int e = l; e < DH; e += 32) d += hrow[e] * hs[e];
#pragma unroll
                for (int o = 16; o; o >>= 1) d += __shfl_xor_sync(0xffffffffu, d, o);
                if (l == 0) dots[tau] = d * lampow[dbase - tau];
            }
            __syncthreads();
            // Ah[tid] = sum_tau dots[tau] * hist[tau][tid]
            float Ah = 0.f;
            for (int tau = 0; tau < nh; tau++)
                Ah = fmaf(dots[tau], hist[(size_t)tau * DH + tid], Ah);

            float v;
            if (!fin) {
                block_gate(hcur * Ah, hcur * hcur, Ah * Ah, kexp, red, scal);
                v = scal[2] * hb + scal[3] * Ah;
            } else {
                v = hb + Ah;
            }
            hcur = block_ln_relu(v, gj, bj, red, scal);
            __syncthreads();
            hs[tid] = hcur;
            __syncthreads();
        }
        if (!fin) hist[(size_t)t * DH + tid] = hcur;
    }
    out[(size_t)b * DH + tid] = hs[tid];
}

// ---------------- launch ----------------
extern "C" void kernel_launch(void* const* d_in, const int* in_sizes, int n_in,
                              void* d_out, int out_size) {
    const float* z     = (const float*)d_in[0];  // [48,96,192]
    const float* Wh    = (const float*)d_in[1];  // [384,384]
    const float* Wg    = (const float*)d_in[2];  // [384,192]
    const float* bh    = (const float*)d_in[3];  // [384]
    const float* lng   = (const float*)d_in[4];  // [384]
    const float* lnb   = (const float*)d_in[5];  // [384]
    const float* alpha = (const float*)d_in[6];  // [1]
    float* out = (float*)d_out;                  // [96,384]

    const int smem_bytes = (47 * DH + DH + 4 * DH + 48 + 48 + 40 + 8) * 4;
    static int configured = 0;
    if (!configured) {
        cudaFuncSetAttribute(rnn_kernel, cudaFuncAttributeMaxDynamicSharedMemorySize, smem_bytes);
        configured = 1;
    }

    transpose_k<<<dim3(12, 12), dim3(32, 8)>>>(Wh, DH, DH, 0);  // -> WT_g
    transpose_k<<<dim3(6, 12), dim3(32, 8)>>>(Wg, DH, DG, 1);   // -> WGT_g
    zp_kernel<<<TT * 6, NTH>>>(z, bh);
    rnn_kernel<<<BB, NTH, smem_bytes>>>(lng, lnb, alpha, out);
}

// round 3
// speedup vs baseline: 1.0546x; 1.0546x over previous
#include <cuda_runtime.h>
#include <cuda_bf16.h>

#define DH 384
#define DG 192
#define TT 48
#define BB 96
#define NTH 384
#define NW 12
#define LAM 0.9f
#define ETA 0.5f
#define LN_EPS 1e-5f

// ---------------- device scratch (allocation-free rule) ----------------
__device__ float WT_g[DH * DH];              // W_h transposed: WT[j*DH + i] = W_h[i*DH + j]
__device__ float WGT_g[DG * DH];             // W_g transposed: WGT[i*DH + j] = W_g[j*DG + i]
__device__ float ZP_g[(size_t)TT * BB * DH]; // z @ W_g^T + b_h

// ---------------- transpose prep ----------------
__global__ void transpose_k(const float* __restrict__ src, int rows, int cols, int which) {
    __shared__ float tile[32][33];
    float* dst = (which == 0) ? WT_g : WGT_g;
    int c0 = blockIdx.x * 32, r0 = blockIdx.y * 32;
    int tx = threadIdx.x, ty = threadIdx.y;
#pragma unroll
    for (int k = 0; k < 4; k++)
        tile[ty + 8 * k][tx] = src[(size_t)(r0 + ty + 8 * k) * cols + c0 + tx];
    __syncthreads();
#pragma unroll
    for (int k = 0; k < 4; k++)
        dst[(size_t)(c0 + ty + 8 * k) * rows + r0 + tx] = tile[tx][ty + 8 * k];
}

// ---------------- z-projection prep: ZP[t][b][j] = sum_i z[t][b][i]*W_g[j][i] + b_h[j] ----------------
__global__ void zp_kernel(const float* __restrict__ z, const float* __restrict__ bh) {
    __shared__ __align__(16) float zs[16 * DG];
    int t = blockIdx.x / 6, bc = blockIdx.x % 6;
    int j = threadIdx.x;
    const float* zsrc = z + ((size_t)t * BB + bc * 16) * DG;
    for (int idx = j; idx < 16 * DG; idx += NTH) zs[idx] = zsrc[idx];
    __syncthreads();
    float acc[16];
    float b0 = bh[j];
#pragma unroll
    for (int m = 0; m < 16; m++) acc[m] = b0;
    const float4* zs4 = (const float4*)zs;
    for (int i4 = 0; i4 < DG / 4; i4++) {
        float w0 = WGT_g[(size_t)(4 * i4 + 0) * DH + j];
        float w1 = WGT_g[(size_t)(4 * i4 + 1) * DH + j];
        float w2 = WGT_g[(size_t)(4 * i4 + 2) * DH + j];
        float w3 = WGT_g[(size_t)(4 * i4 + 3) * DH + j];
#pragma unroll
        for (int m = 0; m < 16; m++) {
            float4 zv = zs4[m * (DG / 4) + i4];
            acc[m] = fmaf(zv.x, w0, acc[m]);
            acc[m] = fmaf(zv.y, w1, acc[m]);
            acc[m] = fmaf(zv.z, w2, acc[m]);
            acc[m] = fmaf(zv.w, w3, acc[m]);
        }
    }
    float* dst = ZP_g + ((size_t)t * BB + bc * 16) * DH + j;
#pragma unroll
    for (int m = 0; m < 16; m++) dst[(size_t)m * DH] = acc[m];
}

// ---------------- main recurrence: one CTA per batch ----------------
// smem layout (floats): hist 47*384 | hs 384 | part 4*384 | dots 48 | lampow 48 | red 96
#define SMEM_FLOATS (47 * DH + DH + 4 * DH + 48 + 48 + 96)

__global__ void __launch_bounds__(NTH, 1)
rnn_kernel(const float* __restrict__ lng, const float* __restrict__ lnb,
           const float* __restrict__ alpha, float* __restrict__ out) {
    extern __shared__ float sm[];
    float* hist   = sm;                  // 47*384
    float* hs     = hist + 47 * DH;      // 384
    float* part   = hs + DH;             // 4*384
    float* dots   = part + 4 * DH;       // 48
    float* lampow = dots + 48;           // 48
    float* red    = lampow + 48;         // 96 (layout: red[v*12 + warp])

    const int b   = blockIdx.x;
    const int tid = threadIdx.x;
    const int w   = tid >> 5, l = tid & 31;
    const int q   = tid / 96, c = tid % 96;

    float alf  = alpha[0];
    float kexp = (alf >= 0.f) ? (1.f + log1pf(expf(alf)))
                              : (1.f / (1.f + log1pf(expf(-alf))));
    float gj = lng[tid], bj = lnb[tid];

    if (tid < TT) lampow[tid] = ETA * powf(LAM, (float)tid);
    hs[tid] = 0.f;  // h0 = 0
    __syncthreads();

    const float4* WT4 = (const float4*)WT_g;

    for (int t = 0; t < TT; t++) {
        // ---------- gemv: hb = W_h @ hs + ZP[t][b] ----------
        float zp = ZP_g[((size_t)t * BB + b) * DH + tid];
        const float4* hs4 = (const float4*)hs;
        float4 accA = make_float4(0.f, 0.f, 0.f, 0.f);
        float4 accB = make_float4(0.f, 0.f, 0.f, 0.f);
        const int jb = q * 24;
#pragma unroll 6
        for (int jj = 0; jj < 24; jj += 2) {
            float4 hv0 = hs4[jb + jj];
            float4 hv1 = hs4[jb + jj + 1];
            int j0 = (jb + jj) * 4;
            float4 w0 = WT4[(size_t)(j0 + 0) * 96 + c];
            float4 w1 = WT4[(size_t)(j0 + 1) * 96 + c];
            float4 w2 = WT4[(size_t)(j0 + 2) * 96 + c];
            float4 w3 = WT4[(size_t)(j0 + 3) * 96 + c];
            float4 w4 = WT4[(size_t)(j0 + 4) * 96 + c];
            float4 w5 = WT4[(size_t)(j0 + 5) * 96 + c];
            float4 w6 = WT4[(size_t)(j0 + 6) * 96 + c];
            float4 w7 = WT4[(size_t)(j0 + 7) * 96 + c];
            accA.x = fmaf(hv0.x, w0.x, fmaf(hv0.y, w1.x, fmaf(hv0.z, w2.x, fmaf(hv0.w, w3.x, accA.x))));
            accA.y = fmaf(hv0.x, w0.y, fmaf(hv0.y, w1.y, fmaf(hv0.z, w2.y, fmaf(hv0.w, w3.y, accA.y))));
            accA.z = fmaf(hv0.x, w0.z, fmaf(hv0.y, w1.z, fmaf(hv0.z, w2.z, fmaf(hv0.w, w3.z, accA.z))));
            accA.w = fmaf(hv0.x, w0.w, fmaf(hv0.y, w1.w, fmaf(hv0.z, w2.w, fmaf(hv0.w, w3.w, accA.w))));
            accB.x = fmaf(hv1.x, w4.x, fmaf(hv1.y, w5.x, fmaf(hv1.z, w6.x, fmaf(hv1.w, w7.x, accB.x))));
            accB.y = fmaf(hv1.x, w4.y, fmaf(hv1.y, w5.y, fmaf(hv1.z, w6.y, fmaf(hv1.w, w7.y, accB.y))));
            accB.z = fmaf(hv1.x, w4.z, fmaf(hv1.y, w5.z, fmaf(hv1.z, w6.z, fmaf(hv1.w, w7.z, accB.z))));
            accB.w = fmaf(hv1.x, w4.w, fmaf(hv1.y, w5.w, fmaf(hv1.z, w6.w, fmaf(hv1.w, w7.w, accB.w))));
        }
        float4 acc = make_float4(accA.x + accB.x, accA.y + accB.y,
                                 accA.z + accB.z, accA.w + accB.w);
        __syncthreads();                 // hs reads + prior part reads done
        ((float4*)part)[tid] = acc;      // part[q*384 + 4c + comp]
        __syncthreads();

        float hb = zp;
#pragma unroll
        for (int qq = 0; qq < 4; qq++) hb += part[qq * DH + tid];

        // ---------- LN#1 on hb (fused: warp reduce + all-thread final) ----------
        float s0 = hb, s1 = hb * hb;
#pragma unroll
        for (int o = 16; o; o >>= 1) {
            s0 += __shfl_xor_sync(0xffffffffu, s0, o);
            s1 += __shfl_xor_sync(0xffffffffu, s1, o);
        }
        if (l == 0) { red[0 * NW + w] = s0; red[1 * NW + w] = s1; }
        __syncthreads();
        float Shb = 0.f, Shb2 = 0.f;
#pragma unroll
        for (int i = 0; i < NW; i++) { Shb += red[0 * NW + i]; Shb2 += red[1 * NW + i]; }
        float mean = Shb * (1.f / DH);
        float rstd = rsqrtf(Shb2 * (1.f / DH) - mean * mean + LN_EPS);
        float hcur = fmaxf((hb - mean) * rstd * gj + bj, 0.f);
        hs[tid] = hcur;
        __syncthreads();                 // hcur visible; red free

        const bool fin   = (t == TT - 1);
        const int  nh    = fin ? (TT - 1) : t;
        const int  dbase = fin ? (TT - 2) : (t - 1);

        // ---------- settling loop ----------
        for (int s = 0; s < 3; s++) {
            // dots[tau] = eta*lam^(dbase-tau) * (hist[tau] . hs)
            if (nh > 0) {
                float hsv[12];
#pragma unroll
                for (int i = 0; i < 12; i++) hsv[i] = hs[l + 32 * i];
                for (int tau = w; tau < nh; tau += NW) {
                    const float* hr = hist + (size_t)tau * DH;
                    float d = 0.f;
#pragma unroll
                    for (int i = 0; i < 12; i++) d = fmaf(hr[l + 32 * i], hsv[i], d);
#pragma unroll
                    for (int o = 16; o; o >>= 1) d += __shfl_xor_sync(0xffffffffu, d, o);
                    if (l == 0) dots[tau] = d * lampow[dbase - tau];
                }
            }
            __syncthreads();

            // Ah[tid] = sum_tau dots[tau] * hist[tau][tid]
            float a0 = 0.f, a1 = 0.f, a2 = 0.f, a3 = 0.f;
            int tau = 0;
            for (; tau + 4 <= nh; tau += 4) {
                a0 = fmaf(dots[tau + 0], hist[(size_t)(tau + 0) * DH + tid], a0);
                a1 = fmaf(dots[tau + 1], hist[(size_t)(tau + 1) * DH + tid], a1);
                a2 = fmaf(dots[tau + 2], hist[(size_t)(tau + 2) * DH + tid], a2);
                a3 = fmaf(dots[tau + 3], hist[(size_t)(tau + 3) * DH + tid], a3);
            }
            for (; tau < nh; tau++)
                a0 = fmaf(dots[tau], hist[(size_t)tau * DH + tid], a0);
            float Ah = (a0 + a1) + (a2 + a3);

            // single fused reduction round: 5 sums
            float v0 = hcur * Ah;     // h.Ah  (gate numerator)
            float v1 = hcur * hcur;   // |h|^2
            float v2 = Ah * Ah;       // |Ah|^2
            float v3 = Ah;            // sum Ah
            float v4 = hb * Ah;       // hb.Ah (LN cross term)
#pragma unroll
            for (int o = 16; o; o >>= 1) {
                v0 += __shfl_xor_sync(0xffffffffu, v0, o);
                v1 += __shfl_xor_sync(0xffffffffu, v1, o);
                v2 += __shfl_xor_sync(0xffffffffu, v2, o);
                v3 += __shfl_xor_sync(0xffffffffu, v3, o);
                v4 += __shfl_xor_sync(0xffffffffu, v4, o);
            }
            if (l == 0) {
                red[0 * NW + w] = v0; red[1 * NW + w] = v1; red[2 * NW + w] = v2;
                red[3 * NW + w] = v3; red[4 * NW + w] = v4;
            }
            __syncthreads();
            float D = 0.f, P = 0.f, Q = 0.f, SA = 0.f, SX = 0.f;
#pragma unroll
            for (int i = 0; i < NW; i++) {
                D  += red[0 * NW + i];
                P  += red[1 * NW + i];
                Q  += red[2 * NW + i];
                SA += red[3 * NW + i];
                SX += red[4 * NW + i];
            }
            // gate scalars (redundant per-thread; no serialization)
            float c1, ca;
            if (!fin) {
                float n1 = fmaxf(sqrtf(P), 1e-6f);
                float n2 = fmaxf(sqrtf(Q), 1e-6f);
                float R  = fminf(fmaxf(D / (n1 * n2), 0.f), 1.f);
                float a  = 1.f - exp2f(kexp * log2f(1.f - R));  // == 1-(1-R)^k
                c1 = 1.f - a * a;
                ca = a;
            } else {
                c1 = 1.f; ca = 1.f;
            }
            // analytic LN stats of v = c1*hb + ca*Ah
            float Sv  = c1 * Shb + ca * SA;
            float Sv2 = c1 * c1 * Shb2 + 2.f * c1 * ca * SX + ca * ca * Q;
            float mn  = Sv * (1.f / DH);
            float rs  = rsqrtf(Sv2 * (1.f / DH) - mn * mn + LN_EPS);
            float v   = c1 * hb + ca * Ah;
            hcur = fmaxf((v - mn) * rs * gj + bj, 0.f);
            hs[tid] = hcur;
            __syncthreads();
        }
        if (!fin) hist[(size_t)t * DH + tid] = hcur;
    }
    out[(size_t)b * DH + tid] = hs[tid];
}

// ---------------- launch ----------------
extern "C" void kernel_launch(void* const* d_in, const int* in_sizes, int n_in,
                              void* d_out, int out_size) {
    const float* z     = (const float*)d_in[0];  // [48,96,192]
    const float* Wh    = (const float*)d_in[1];  // [384,384]
    const float* Wg    = (const float*)d_in[2];  // [384,192]
    const float* bh    = (const float*)d_in[3];  // [384]
    const float* lng   = (const float*)d_in[4];  // [384]
    const float* lnb   = (const float*)d_in[5];  // [384]
    const float* alpha = (const float*)d_in[6];  // [1]
    float* out = (float*)d_out;                  // [96,384]

    const int smem_bytes = SMEM_FLOATS * 4;
    static int configured = 0;
    if (!configured) {
        cudaFuncSetAttribute(rnn_kernel, cudaFuncAttributeMaxDynamicSharedMemorySize, smem_bytes);
        configured = 1;
    }

    transpose_k<<<dim3(12, 12), dim3(32, 8)>>>(Wh, DH, DH, 0);  // -> WT_g
    transpose_k<<<dim3(6, 12), dim3(32, 8)>>>(Wg, DH, DG, 1);   // -> WGT_g
    zp_kernel<<<TT * 6, NTH>>>(z, bh);
    rnn_kernel<<<BB, NTH, smem_bytes>>>(lng, lnb, alpha, out);
}